// round 11
// baseline (speedup 1.0000x reference)
#include <cuda_runtime.h>
#include <cuda_bf16.h>

// ---------------------------------------------------------------------------
// GCN_6657199308988 : 3-layer GCN on a fixed graph
//   N_NODES=50000, N_EDGES=500000, IN_F=128, HID=256, EMB=128
// Pipeline:
//   CSR build (counting sort by dst)
//   agg1 = segsum(x)            [N,128]   -> bufA
//   h1   = relu(agg1@W1 + b1)   [N,256]   -> bufB
//   agg2 = segsum(h1)           [N,256]   -> bufA
//   h2   = relu(agg2@W2 + b2)   [N,256]   -> bufB
//   t3   = h2@W3                [N,128]   -> bufA   (segsum commutes with @W3)
//   out  = mean_n relu(segsum(t3) + b3)   -> [128]
// ---------------------------------------------------------------------------

#define N_NODES 50000
#define N_EDGES 500000

// ---- scratch (static device globals; allocation-free) ----
__device__ float g_bufA[(size_t)N_NODES * 256];  // 51.2 MB
__device__ float g_bufB[(size_t)N_NODES * 256];  // 51.2 MB
__device__ int   g_cnt[N_NODES];
__device__ int   g_off[N_NODES + 1];
__device__ int   g_cur[N_NODES];
__device__ int   g_csr[N_EDGES];
__device__ float g_acc[128];

// ---------------------------------------------------------------------------
// CSR build
// ---------------------------------------------------------------------------
__global__ void zero_kernel() {
    int i = blockIdx.x * blockDim.x + threadIdx.x;
    if (i < N_NODES) g_cnt[i] = 0;
    if (i < 128)     g_acc[i] = 0.f;
}

__global__ void hist_kernel(const int* __restrict__ dst) {
    int i = blockIdx.x * blockDim.x + threadIdx.x;
    if (i < N_EDGES) atomicAdd(&g_cnt[dst[i]], 1);
}

// single-block exclusive scan over g_cnt -> g_off, g_cur
__global__ void scan_kernel() {
    __shared__ int sums[1024];
    const int t  = threadIdx.x;
    const int CH = (N_NODES + 1023) / 1024;   // 49
    const int start = t * CH;
    int s = 0;
    for (int i = 0; i < CH; i++) {
        int idx = start + i;
        if (idx < N_NODES) s += g_cnt[idx];
    }
    sums[t] = s;
    __syncthreads();
    // inclusive Hillis-Steele scan
    for (int d = 1; d < 1024; d <<= 1) {
        int v = (t >= d) ? sums[t - d] : 0;
        __syncthreads();
        sums[t] += v;
        __syncthreads();
    }
    int run = sums[t] - s;   // exclusive prefix for this chunk
    for (int i = 0; i < CH; i++) {
        int idx = start + i;
        if (idx < N_NODES) {
            g_off[idx] = run;
            g_cur[idx] = run;
            run += g_cnt[idx];
        }
    }
    if (t == 1023) g_off[N_NODES] = run;   // thread 1023's chunk is empty -> run == total
}

__global__ void scatter_kernel(const int* __restrict__ src, const int* __restrict__ dst) {
    int i = blockIdx.x * blockDim.x + threadIdx.x;
    if (i < N_EDGES) {
        int p = atomicAdd(&g_cur[dst[i]], 1);
        g_csr[p] = src[i];
    }
}

// ---------------------------------------------------------------------------
// Aggregation: one warp per destination node, CSR segment sum
// ---------------------------------------------------------------------------
__device__ __forceinline__ void f4add(float4& a, const float4& v) {
    a.x += v.x; a.y += v.y; a.z += v.z; a.w += v.w;
}

// F=128: x (external) -> g_bufA
__global__ void agg128_kernel(const float* __restrict__ Hext) {
    int w    = (blockIdx.x * blockDim.x + threadIdx.x) >> 5;
    int lane = threadIdx.x & 31;
    if (w >= N_NODES) return;
    const float4* H = reinterpret_cast<const float4*>(Hext);
    int s = g_off[w], e = g_off[w + 1];
    float4 acc = make_float4(0.f, 0.f, 0.f, 0.f);
    int i = s;
    for (; i + 2 <= e; i += 2) {
        int s0 = g_csr[i], s1 = g_csr[i + 1];
        float4 v0 = H[s0 * 32 + lane];
        float4 v1 = H[s1 * 32 + lane];
        f4add(acc, v0); f4add(acc, v1);
    }
    if (i < e) {
        int s0 = g_csr[i];
        f4add(acc, H[s0 * 32 + lane]);
    }
    reinterpret_cast<float4*>(g_bufA)[w * 32 + lane] = acc;
}

// F=256: g_bufB -> g_bufA
__global__ void agg256_kernel() {
    int w    = (blockIdx.x * blockDim.x + threadIdx.x) >> 5;
    int lane = threadIdx.x & 31;
    if (w >= N_NODES) return;
    const float4* H = reinterpret_cast<const float4*>(g_bufB);
    int s = g_off[w], e = g_off[w + 1];
    float4 a0 = make_float4(0.f, 0.f, 0.f, 0.f);
    float4 a1 = make_float4(0.f, 0.f, 0.f, 0.f);
    int i = s;
    for (; i + 2 <= e; i += 2) {
        int s0 = g_csr[i], s1 = g_csr[i + 1];
        float4 u0 = H[s0 * 64 + lane];
        float4 u1 = H[s0 * 64 + 32 + lane];
        float4 v0 = H[s1 * 64 + lane];
        float4 v1 = H[s1 * 64 + 32 + lane];
        f4add(a0, u0); f4add(a1, u1);
        f4add(a0, v0); f4add(a1, v1);
    }
    if (i < e) {
        int s0 = g_csr[i];
        f4add(a0, H[s0 * 64 + lane]);
        f4add(a1, H[s0 * 64 + 32 + lane]);
    }
    float4* O = reinterpret_cast<float4*>(g_bufA);
    O[w * 64 + lane]      = a0;
    O[w * 64 + 32 + lane] = a1;
}

// F=128 final: segsum(g_bufA) + b3, relu, block-reduced mean accumulation
__global__ void agg_final_kernel(const float* __restrict__ b3) {
    __shared__ float s_acc[128];
    if (threadIdx.x < 128) s_acc[threadIdx.x] = 0.f;
    __syncthreads();

    int gw   = (blockIdx.x * blockDim.x + threadIdx.x) >> 5;
    int nw   = (gridDim.x * blockDim.x) >> 5;
    int lane = threadIdx.x & 31;
    const float4* T = reinterpret_cast<const float4*>(g_bufA);
    float4 bb = reinterpret_cast<const float4*>(b3)[lane];
    float4 tot = make_float4(0.f, 0.f, 0.f, 0.f);

    for (int node = gw; node < N_NODES; node += nw) {
        int s = g_off[node], e = g_off[node + 1];
        float4 a = make_float4(0.f, 0.f, 0.f, 0.f);
        int i = s;
        for (; i + 2 <= e; i += 2) {
            int s0 = g_csr[i], s1 = g_csr[i + 1];
            f4add(a, T[s0 * 32 + lane]);
            f4add(a, T[s1 * 32 + lane]);
        }
        if (i < e) f4add(a, T[g_csr[i] * 32 + lane]);
        tot.x += fmaxf(a.x + bb.x, 0.f);
        tot.y += fmaxf(a.y + bb.y, 0.f);
        tot.z += fmaxf(a.z + bb.z, 0.f);
        tot.w += fmaxf(a.w + bb.w, 0.f);
    }
    atomicAdd(&s_acc[lane * 4 + 0], tot.x);
    atomicAdd(&s_acc[lane * 4 + 1], tot.y);
    atomicAdd(&s_acc[lane * 4 + 2], tot.z);
    atomicAdd(&s_acc[lane * 4 + 3], tot.w);
    __syncthreads();
    if (threadIdx.x < 128) atomicAdd(&g_acc[threadIdx.x], s_acc[threadIdx.x]);
}

__global__ void finalize_kernel(float* __restrict__ out) {
    int i = threadIdx.x;
    if (i < 128) out[i] = g_acc[i] * (1.0f / (float)N_NODES);
}

// ---------------------------------------------------------------------------
// fp32 SGEMM: C[M,N] = op(A[M,K] @ B[K,N] + bias), op = relu if do_relu
// A/C are internal ping-pong buffers selected by `ab`:
//   ab==0: A=g_bufA, C=g_bufB      ab==1: A=g_bufB, C=g_bufA
// BM=128, BN=128, BK=16, TM=TN=8, 256 threads
// ---------------------------------------------------------------------------
__global__ __launch_bounds__(256) void sgemm_kernel(
    const float* __restrict__ B, const float* __restrict__ bias,
    int M, int N, int K, int do_relu, int ab)
{
    constexpr int BM = 128, BN = 128, BK = 16, TM = 8, TN = 8;
    __shared__ float As[BK][BM];
    __shared__ float Bs[BK][BN];

    const float* __restrict__ A = ab ? g_bufB : g_bufA;
    float* __restrict__       C = ab ? g_bufA : g_bufB;

    const int tid   = threadIdx.x;
    const int brow0 = blockIdx.x * BM;
    const int bcol0 = blockIdx.y * BN;
    const int tr = (tid / (BN / TN)) * TM;   // 0..120
    const int tc = (tid % (BN / TN)) * TN;   // 0..120

    float acc[TM][TN];
#pragma unroll
    for (int i = 0; i < TM; i++)
#pragma unroll
        for (int j = 0; j < TN; j++) acc[i][j] = 0.f;

    for (int k0 = 0; k0 < K; k0 += BK) {
        // load A tile (BM x BK), stored transposed As[k][m]
#pragma unroll
        for (int l = 0; l < 2; l++) {
            int idx = tid + 256 * l;         // 0..511
            int row = idx >> 2;              // 0..127
            int kq  = (idx & 3) << 2;        // 0,4,8,12
            float4 v = make_float4(0.f, 0.f, 0.f, 0.f);
            int gr = brow0 + row;
            if (gr < M) v = *reinterpret_cast<const float4*>(&A[(size_t)gr * K + k0 + kq]);
            As[kq + 0][row] = v.x;
            As[kq + 1][row] = v.y;
            As[kq + 2][row] = v.z;
            As[kq + 3][row] = v.w;
        }
        // load B tile (BK x BN)
#pragma unroll
        for (int l = 0; l < 2; l++) {
            int idx = tid + 256 * l;
            int r   = idx >> 5;              // 0..15
            int c4  = (idx & 31) << 2;       // 0..124
            float4 v = *reinterpret_cast<const float4*>(&B[(size_t)(k0 + r) * N + bcol0 + c4]);
            *reinterpret_cast<float4*>(&Bs[r][c4]) = v;
        }
        __syncthreads();

#pragma unroll
        for (int kk = 0; kk < BK; kk++) {
            float a[TM], b[TN];
#pragma unroll
            for (int i = 0; i < TM; i += 4)
                *reinterpret_cast<float4*>(&a[i]) =
                    *reinterpret_cast<const float4*>(&As[kk][tr + i]);
#pragma unroll
            for (int j = 0; j < TN; j += 4)
                *reinterpret_cast<float4*>(&b[j]) =
                    *reinterpret_cast<const float4*>(&Bs[kk][tc + j]);
#pragma unroll
            for (int i = 0; i < TM; i++)
#pragma unroll
                for (int j = 0; j < TN; j++)
                    acc[i][j] = fmaf(a[i], b[j], acc[i][j]);
        }
        __syncthreads();
    }

    // epilogue: bias + relu + store
#pragma unroll
    for (int i = 0; i < TM; i++) {
        int gr = brow0 + tr + i;
        if (gr >= M) continue;
#pragma unroll
        for (int j = 0; j < TN; j += 4) {
            float4 v = make_float4(acc[i][j], acc[i][j + 1], acc[i][j + 2], acc[i][j + 3]);
            if (bias) {
                float4 bb = *reinterpret_cast<const float4*>(&bias[bcol0 + tc + j]);
                v.x += bb.x; v.y += bb.y; v.z += bb.z; v.w += bb.w;
            }
            if (do_relu) {
                v.x = fmaxf(v.x, 0.f); v.y = fmaxf(v.y, 0.f);
                v.z = fmaxf(v.z, 0.f); v.w = fmaxf(v.w, 0.f);
            }
            *reinterpret_cast<float4*>(&C[(size_t)gr * N + bcol0 + tc + j]) = v;
        }
    }
}

// ---------------------------------------------------------------------------
// launch
// ---------------------------------------------------------------------------
extern "C" void kernel_launch(void* const* d_in, const int* in_sizes, int n_in,
                              void* d_out, int out_size)
{
    const float* x   = (const float*)d_in[0];
    const int*   src = (const int*)  d_in[1];
    const int*   dst = (const int*)  d_in[2];
    const float* W1  = (const float*)d_in[3];
    const float* b1  = (const float*)d_in[4];
    const float* W2  = (const float*)d_in[5];
    const float* b2  = (const float*)d_in[6];
    const float* W3  = (const float*)d_in[7];
    const float* b3  = (const float*)d_in[8];
    float* out = (float*)d_out;
    (void)in_sizes; (void)n_in; (void)out_size;

    // CSR build
    zero_kernel   <<<(N_NODES + 255) / 256, 256>>>();
    hist_kernel   <<<(N_EDGES + 255) / 256, 256>>>(dst);
    scan_kernel   <<<1, 1024>>>();
    scatter_kernel<<<(N_EDGES + 255) / 256, 256>>>(src, dst);

    const int aggBlocks = (N_NODES + 7) / 8;   // 8 warps/block, 1 warp/node
    dim3 gemm2col((N_NODES + 127) / 128, 2);
    dim3 gemm1col((N_NODES + 127) / 128, 1);

    // layer 1: agg(x) -> bufA ; relu(bufA@W1+b1) -> bufB
    agg128_kernel<<<aggBlocks, 256>>>(x);
    sgemm_kernel<<<gemm2col, 256>>>(W1, b1, N_NODES, 256, 128, 1, 0);

    // layer 2: agg(bufB) -> bufA ; relu(bufA@W2+b2) -> bufB
    agg256_kernel<<<aggBlocks, 256>>>();
    sgemm_kernel<<<gemm2col, 256>>>(W2, b2, N_NODES, 256, 256, 1, 0);

    // layer 3 (reordered): bufB@W3 -> bufA ; mean_n relu(segsum(bufA) + b3)
    sgemm_kernel<<<gemm1col, 256>>>(W3, nullptr, N_NODES, 128, 256, 0, 1);
    agg_final_kernel<<<592, 256>>>(b3);
    finalize_kernel<<<1, 128>>>(out);
}

// round 12
// speedup vs baseline: 1.0029x; 1.0029x over previous
#include <cuda_runtime.h>
#include <cuda_bf16.h>

// ---------------------------------------------------------------------------
// GCN_6657199308988 : 3-layer GCN on a fixed graph
//   N_NODES=50000, N_EDGES=500000, IN_F=128, HID=256, EMB=128
// Pipeline:
//   CSR build (counting sort by dst)
//   agg1 = segsum(x)            [N,128]   -> bufA
//   h1   = relu(agg1@W1 + b1)   [N,256]   -> bufB
//   agg2 = segsum(h1)           [N,256]   -> bufA
//   h2   = relu(agg2@W2 + b2)   [N,256]   -> bufB
//   t3   = h2@W3                [N,128]   -> bufA   (segsum commutes with @W3)
//   out  = mean_n relu(segsum(t3) + b3)   -> [128]
// ---------------------------------------------------------------------------

#define N_NODES 50000
#define N_EDGES 500000

// ---- scratch (static device globals; allocation-free) ----
__device__ float g_bufA[(size_t)N_NODES * 256];  // 51.2 MB
__device__ float g_bufB[(size_t)N_NODES * 256];  // 51.2 MB
__device__ int   g_cnt[N_NODES];
__device__ int   g_off[N_NODES + 1];
__device__ int   g_cur[N_NODES];
__device__ int   g_csr[N_EDGES];
__device__ float g_acc[128];

// ---------------------------------------------------------------------------
// CSR build
// ---------------------------------------------------------------------------
__global__ void zero_kernel() {
    int i = blockIdx.x * blockDim.x + threadIdx.x;
    if (i < N_NODES) g_cnt[i] = 0;
    if (i < 128)     g_acc[i] = 0.f;
}

__global__ void hist_kernel(const int* __restrict__ dst) {
    int i = blockIdx.x * blockDim.x + threadIdx.x;
    if (i < N_EDGES) atomicAdd(&g_cnt[dst[i]], 1);
}

// single-block exclusive scan over g_cnt -> g_off, g_cur
__global__ void scan_kernel() {
    __shared__ int sums[1024];
    const int t  = threadIdx.x;
    const int CH = (N_NODES + 1023) / 1024;   // 49
    const int start = t * CH;
    int s = 0;
    for (int i = 0; i < CH; i++) {
        int idx = start + i;
        if (idx < N_NODES) s += g_cnt[idx];
    }
    sums[t] = s;
    __syncthreads();
    // inclusive Hillis-Steele scan
    for (int d = 1; d < 1024; d <<= 1) {
        int v = (t >= d) ? sums[t - d] : 0;
        __syncthreads();
        sums[t] += v;
        __syncthreads();
    }
    int run = sums[t] - s;   // exclusive prefix for this chunk
    for (int i = 0; i < CH; i++) {
        int idx = start + i;
        if (idx < N_NODES) {
            g_off[idx] = run;
            g_cur[idx] = run;
            run += g_cnt[idx];
        }
    }
    if (t == 1023) g_off[N_NODES] = run;   // thread 1023's chunk is empty -> run == total
}

__global__ void scatter_kernel(const int* __restrict__ src, const int* __restrict__ dst) {
    int i = blockIdx.x * blockDim.x + threadIdx.x;
    if (i < N_EDGES) {
        int p = atomicAdd(&g_cur[dst[i]], 1);
        g_csr[p] = src[i];
    }
}

// ---------------------------------------------------------------------------
// Aggregation: one warp per destination node, CSR segment sum
// ---------------------------------------------------------------------------
__device__ __forceinline__ void f4add(float4& a, const float4& v) {
    a.x += v.x; a.y += v.y; a.z += v.z; a.w += v.w;
}

// F=128: x (external) -> g_bufA
__global__ void agg128_kernel(const float* __restrict__ Hext) {
    int w    = (blockIdx.x * blockDim.x + threadIdx.x) >> 5;
    int lane = threadIdx.x & 31;
    if (w >= N_NODES) return;
    const float4* H = reinterpret_cast<const float4*>(Hext);
    int s = g_off[w], e = g_off[w + 1];
    float4 acc = make_float4(0.f, 0.f, 0.f, 0.f);
    int i = s;
    for (; i + 2 <= e; i += 2) {
        int s0 = g_csr[i], s1 = g_csr[i + 1];
        float4 v0 = H[s0 * 32 + lane];
        float4 v1 = H[s1 * 32 + lane];
        f4add(acc, v0); f4add(acc, v1);
    }
    if (i < e) {
        int s0 = g_csr[i];
        f4add(acc, H[s0 * 32 + lane]);
    }
    reinterpret_cast<float4*>(g_bufA)[w * 32 + lane] = acc;
}

// F=256: g_bufB -> g_bufA
__global__ void agg256_kernel() {
    int w    = (blockIdx.x * blockDim.x + threadIdx.x) >> 5;
    int lane = threadIdx.x & 31;
    if (w >= N_NODES) return;
    const float4* H = reinterpret_cast<const float4*>(g_bufB);
    int s = g_off[w], e = g_off[w + 1];
    float4 a0 = make_float4(0.f, 0.f, 0.f, 0.f);
    float4 a1 = make_float4(0.f, 0.f, 0.f, 0.f);
    int i = s;
    for (; i + 2 <= e; i += 2) {
        int s0 = g_csr[i], s1 = g_csr[i + 1];
        float4 u0 = H[s0 * 64 + lane];
        float4 u1 = H[s0 * 64 + 32 + lane];
        float4 v0 = H[s1 * 64 + lane];
        float4 v1 = H[s1 * 64 + 32 + lane];
        f4add(a0, u0); f4add(a1, u1);
        f4add(a0, v0); f4add(a1, v1);
    }
    if (i < e) {
        int s0 = g_csr[i];
        f4add(a0, H[s0 * 64 + lane]);
        f4add(a1, H[s0 * 64 + 32 + lane]);
    }
    float4* O = reinterpret_cast<float4*>(g_bufA);
    O[w * 64 + lane]      = a0;
    O[w * 64 + 32 + lane] = a1;
}

// F=128 final: segsum(g_bufA) + b3, relu, block-reduced mean accumulation
__global__ void agg_final_kernel(const float* __restrict__ b3) {
    __shared__ float s_acc[128];
    if (threadIdx.x < 128) s_acc[threadIdx.x] = 0.f;
    __syncthreads();

    int gw   = (blockIdx.x * blockDim.x + threadIdx.x) >> 5;
    int nw   = (gridDim.x * blockDim.x) >> 5;
    int lane = threadIdx.x & 31;
    const float4* T = reinterpret_cast<const float4*>(g_bufA);
    float4 bb = reinterpret_cast<const float4*>(b3)[lane];
    float4 tot = make_float4(0.f, 0.f, 0.f, 0.f);

    for (int node = gw; node < N_NODES; node += nw) {
        int s = g_off[node], e = g_off[node + 1];
        float4 a = make_float4(0.f, 0.f, 0.f, 0.f);
        int i = s;
        for (; i + 2 <= e; i += 2) {
            int s0 = g_csr[i], s1 = g_csr[i + 1];
            f4add(a, T[s0 * 32 + lane]);
            f4add(a, T[s1 * 32 + lane]);
        }
        if (i < e) f4add(a, T[g_csr[i] * 32 + lane]);
        tot.x += fmaxf(a.x + bb.x, 0.f);
        tot.y += fmaxf(a.y + bb.y, 0.f);
        tot.z += fmaxf(a.z + bb.z, 0.f);
        tot.w += fmaxf(a.w + bb.w, 0.f);
    }
    atomicAdd(&s_acc[lane * 4 + 0], tot.x);
    atomicAdd(&s_acc[lane * 4 + 1], tot.y);
    atomicAdd(&s_acc[lane * 4 + 2], tot.z);
    atomicAdd(&s_acc[lane * 4 + 3], tot.w);
    __syncthreads();
    if (threadIdx.x < 128) atomicAdd(&g_acc[threadIdx.x], s_acc[threadIdx.x]);
}

__global__ void finalize_kernel(float* __restrict__ out) {
    int i = threadIdx.x;
    if (i < 128) out[i] = g_acc[i] * (1.0f / (float)N_NODES);
}

// ---------------------------------------------------------------------------
// fp32 SGEMM: C[M,N] = op(A[M,K] @ B[K,N] + bias), op = relu if do_relu
// A/C are internal ping-pong buffers selected by `ab`:
//   ab==0: A=g_bufA, C=g_bufB      ab==1: A=g_bufB, C=g_bufA
// BM=128, BN=128, BK=16, TM=TN=8, 256 threads
// ---------------------------------------------------------------------------
__global__ __launch_bounds__(256) void sgemm_kernel(
    const float* __restrict__ B, const float* __restrict__ bias,
    int M, int N, int K, int do_relu, int ab)
{
    constexpr int BM = 128, BN = 128, BK = 16, TM = 8, TN = 8;
    __shared__ float As[BK][BM];
    __shared__ float Bs[BK][BN];

    const float* __restrict__ A = ab ? g_bufB : g_bufA;
    float* __restrict__       C = ab ? g_bufA : g_bufB;

    const int tid   = threadIdx.x;
    const int brow0 = blockIdx.x * BM;
    const int bcol0 = blockIdx.y * BN;
    const int tr = (tid / (BN / TN)) * TM;   // 0..120
    const int tc = (tid % (BN / TN)) * TN;   // 0..120

    float acc[TM][TN];
#pragma unroll
    for (int i = 0; i < TM; i++)
#pragma unroll
        for (int j = 0; j < TN; j++) acc[i][j] = 0.f;

    for (int k0 = 0; k0 < K; k0 += BK) {
        // load A tile (BM x BK), stored transposed As[k][m]
#pragma unroll
        for (int l = 0; l < 2; l++) {
            int idx = tid + 256 * l;         // 0..511
            int row = idx >> 2;              // 0..127
            int kq  = (idx & 3) << 2;        // 0,4,8,12
            float4 v = make_float4(0.f, 0.f, 0.f, 0.f);
            int gr = brow0 + row;
            if (gr < M) v = *reinterpret_cast<const float4*>(&A[(size_t)gr * K + k0 + kq]);
            As[kq + 0][row] = v.x;
            As[kq + 1][row] = v.y;
            As[kq + 2][row] = v.z;
            As[kq + 3][row] = v.w;
        }
        // load B tile (BK x BN)
#pragma unroll
        for (int l = 0; l < 2; l++) {
            int idx = tid + 256 * l;
            int r   = idx >> 5;              // 0..15
            int c4  = (idx & 31) << 2;       // 0..124
            float4 v = *reinterpret_cast<const float4*>(&B[(size_t)(k0 + r) * N + bcol0 + c4]);
            *reinterpret_cast<float4*>(&Bs[r][c4]) = v;
        }
        __syncthreads();

#pragma unroll
        for (int kk = 0; kk < BK; kk++) {
            float a[TM], b[TN];
#pragma unroll
            for (int i = 0; i < TM; i += 4)
                *reinterpret_cast<float4*>(&a[i]) =
                    *reinterpret_cast<const float4*>(&As[kk][tr + i]);
#pragma unroll
            for (int j = 0; j < TN; j += 4)
                *reinterpret_cast<float4*>(&b[j]) =
                    *reinterpret_cast<const float4*>(&Bs[kk][tc + j]);
#pragma unroll
            for (int i = 0; i < TM; i++)
#pragma unroll
                for (int j = 0; j < TN; j++)
                    acc[i][j] = fmaf(a[i], b[j], acc[i][j]);
        }
        __syncthreads();
    }

    // epilogue: bias + relu + store
#pragma unroll
    for (int i = 0; i < TM; i++) {
        int gr = brow0 + tr + i;
        if (gr >= M) continue;
#pragma unroll
        for (int j = 0; j < TN; j += 4) {
            float4 v = make_float4(acc[i][j], acc[i][j + 1], acc[i][j + 2], acc[i][j + 3]);
            if (bias) {
                float4 bb = *reinterpret_cast<const float4*>(&bias[bcol0 + tc + j]);
                v.x += bb.x; v.y += bb.y; v.z += bb.z; v.w += bb.w;
            }
            if (do_relu) {
                v.x = fmaxf(v.x, 0.f); v.y = fmaxf(v.y, 0.f);
                v.z = fmaxf(v.z, 0.f); v.w = fmaxf(v.w, 0.f);
            }
            *reinterpret_cast<float4*>(&C[(size_t)gr * N + bcol0 + tc + j]) = v;
        }
    }
}

// ---------------------------------------------------------------------------
// launch
// ---------------------------------------------------------------------------
extern "C" void kernel_launch(void* const* d_in, const int* in_sizes, int n_in,
                              void* d_out, int out_size)
{
    const float* x   = (const float*)d_in[0];
    const int*   src = (const int*)  d_in[1];
    const int*   dst = (const int*)  d_in[2];
    const float* W1  = (const float*)d_in[3];
    const float* b1  = (const float*)d_in[4];
    const float* W2  = (const float*)d_in[5];
    const float* b2  = (const float*)d_in[6];
    const float* W3  = (const float*)d_in[7];
    const float* b3  = (const float*)d_in[8];
    float* out = (float*)d_out;
    (void)in_sizes; (void)n_in; (void)out_size;

    // CSR build
    zero_kernel   <<<(N_NODES + 255) / 256, 256>>>();
    hist_kernel   <<<(N_EDGES + 255) / 256, 256>>>(dst);
    scan_kernel   <<<1, 1024>>>();
    scatter_kernel<<<(N_EDGES + 255) / 256, 256>>>(src, dst);

    const int aggBlocks = (N_NODES + 7) / 8;   // 8 warps/block, 1 warp/node
    dim3 gemm2col((N_NODES + 127) / 128, 2);
    dim3 gemm1col((N_NODES + 127) / 128, 1);

    // layer 1: agg(x) -> bufA ; relu(bufA@W1+b1) -> bufB
    agg128_kernel<<<aggBlocks, 256>>>(x);
    sgemm_kernel<<<gemm2col, 256>>>(W1, b1, N_NODES, 256, 128, 1, 0);

    // layer 2: agg(bufB) -> bufA ; relu(bufA@W2+b2) -> bufB
    agg256_kernel<<<aggBlocks, 256>>>();
    sgemm_kernel<<<gemm2col, 256>>>(W2, b2, N_NODES, 256, 256, 1, 0);

    // layer 3 (reordered): bufB@W3 -> bufA ; mean_n relu(segsum(bufA) + b3)
    sgemm_kernel<<<gemm1col, 256>>>(W3, nullptr, N_NODES, 128, 256, 0, 1);
    agg_final_kernel<<<592, 256>>>(b3);
    finalize_kernel<<<1, 128>>>(out);
}

// round 13
// speedup vs baseline: 1.0040x; 1.0011x over previous
#include <cuda_runtime.h>
#include <cuda_bf16.h>

// ---------------------------------------------------------------------------
// GCN_6657199308988 : 3-layer GCN on a fixed graph
//   N_NODES=50000, N_EDGES=500000, IN_F=128, HID=256, EMB=128
// Pipeline:
//   CSR build (counting sort by dst)
//   agg1 = segsum(x)            [N,128]   -> bufA
//   h1   = relu(agg1@W1 + b1)   [N,256]   -> bufB
//   agg2 = segsum(h1)           [N,256]   -> bufA
//   h2   = relu(agg2@W2 + b2)   [N,256]   -> bufB
//   t3   = h2@W3                [N,128]   -> bufA   (segsum commutes with @W3)
//   out  = mean_n relu(segsum(t3) + b3)   -> [128]
// ---------------------------------------------------------------------------

#define N_NODES 50000
#define N_EDGES 500000

// ---- scratch (static device globals; allocation-free) ----
__device__ float g_bufA[(size_t)N_NODES * 256];  // 51.2 MB
__device__ float g_bufB[(size_t)N_NODES * 256];  // 51.2 MB
__device__ int   g_cnt[N_NODES];
__device__ int   g_off[N_NODES + 1];
__device__ int   g_cur[N_NODES];
__device__ int   g_csr[N_EDGES];
__device__ float g_acc[128];

// ---------------------------------------------------------------------------
// CSR build
// ---------------------------------------------------------------------------
__global__ void zero_kernel() {
    int i = blockIdx.x * blockDim.x + threadIdx.x;
    if (i < N_NODES) g_cnt[i] = 0;
    if (i < 128)     g_acc[i] = 0.f;
}

__global__ void hist_kernel(const int* __restrict__ dst) {
    int i = blockIdx.x * blockDim.x + threadIdx.x;
    if (i < N_EDGES) atomicAdd(&g_cnt[dst[i]], 1);
}

// single-block exclusive scan over g_cnt -> g_off, g_cur
__global__ void scan_kernel() {
    __shared__ int sums[1024];
    const int t  = threadIdx.x;
    const int CH = (N_NODES + 1023) / 1024;   // 49
    const int start = t * CH;
    int s = 0;
    for (int i = 0; i < CH; i++) {
        int idx = start + i;
        if (idx < N_NODES) s += g_cnt[idx];
    }
    sums[t] = s;
    __syncthreads();
    // inclusive Hillis-Steele scan
    for (int d = 1; d < 1024; d <<= 1) {
        int v = (t >= d) ? sums[t - d] : 0;
        __syncthreads();
        sums[t] += v;
        __syncthreads();
    }
    int run = sums[t] - s;   // exclusive prefix for this chunk
    for (int i = 0; i < CH; i++) {
        int idx = start + i;
        if (idx < N_NODES) {
            g_off[idx] = run;
            g_cur[idx] = run;
            run += g_cnt[idx];
        }
    }
    if (t == 1023) g_off[N_NODES] = run;   // thread 1023's chunk is empty -> run == total
}

__global__ void scatter_kernel(const int* __restrict__ src, const int* __restrict__ dst) {
    int i = blockIdx.x * blockDim.x + threadIdx.x;
    if (i < N_EDGES) {
        int p = atomicAdd(&g_cur[dst[i]], 1);
        g_csr[p] = src[i];
    }
}

// ---------------------------------------------------------------------------
// Aggregation: one warp per destination node, CSR segment sum
// ---------------------------------------------------------------------------
__device__ __forceinline__ void f4add(float4& a, const float4& v) {
    a.x += v.x; a.y += v.y; a.z += v.z; a.w += v.w;
}

// F=128: x (external) -> g_bufA
__global__ void agg128_kernel(const float* __restrict__ Hext) {
    int w    = (blockIdx.x * blockDim.x + threadIdx.x) >> 5;
    int lane = threadIdx.x & 31;
    if (w >= N_NODES) return;
    const float4* H = reinterpret_cast<const float4*>(Hext);
    int s = g_off[w], e = g_off[w + 1];
    float4 acc = make_float4(0.f, 0.f, 0.f, 0.f);
    int i = s;
    for (; i + 2 <= e; i += 2) {
        int s0 = g_csr[i], s1 = g_csr[i + 1];
        float4 v0 = H[s0 * 32 + lane];
        float4 v1 = H[s1 * 32 + lane];
        f4add(acc, v0); f4add(acc, v1);
    }
    if (i < e) {
        int s0 = g_csr[i];
        f4add(acc, H[s0 * 32 + lane]);
    }
    reinterpret_cast<float4*>(g_bufA)[w * 32 + lane] = acc;
}

// F=256: g_bufB -> g_bufA
__global__ void agg256_kernel() {
    int w    = (blockIdx.x * blockDim.x + threadIdx.x) >> 5;
    int lane = threadIdx.x & 31;
    if (w >= N_NODES) return;
    const float4* H = reinterpret_cast<const float4*>(g_bufB);
    int s = g_off[w], e = g_off[w + 1];
    float4 a0 = make_float4(0.f, 0.f, 0.f, 0.f);
    float4 a1 = make_float4(0.f, 0.f, 0.f, 0.f);
    int i = s;
    for (; i + 2 <= e; i += 2) {
        int s0 = g_csr[i], s1 = g_csr[i + 1];
        float4 u0 = H[s0 * 64 + lane];
        float4 u1 = H[s0 * 64 + 32 + lane];
        float4 v0 = H[s1 * 64 + lane];
        float4 v1 = H[s1 * 64 + 32 + lane];
        f4add(a0, u0); f4add(a1, u1);
        f4add(a0, v0); f4add(a1, v1);
    }
    if (i < e) {
        int s0 = g_csr[i];
        f4add(a0, H[s0 * 64 + lane]);
        f4add(a1, H[s0 * 64 + 32 + lane]);
    }
    float4* O = reinterpret_cast<float4*>(g_bufA);
    O[w * 64 + lane]      = a0;
    O[w * 64 + 32 + lane] = a1;
}

// F=128 final: segsum(g_bufA) + b3, relu, block-reduced mean accumulation
__global__ void agg_final_kernel(const float* __restrict__ b3) {
    __shared__ float s_acc[128];
    if (threadIdx.x < 128) s_acc[threadIdx.x] = 0.f;
    __syncthreads();

    int gw   = (blockIdx.x * blockDim.x + threadIdx.x) >> 5;
    int nw   = (gridDim.x * blockDim.x) >> 5;
    int lane = threadIdx.x & 31;
    const float4* T = reinterpret_cast<const float4*>(g_bufA);
    float4 bb = reinterpret_cast<const float4*>(b3)[lane];
    float4 tot = make_float4(0.f, 0.f, 0.f, 0.f);

    for (int node = gw; node < N_NODES; node += nw) {
        int s = g_off[node], e = g_off[node + 1];
        float4 a = make_float4(0.f, 0.f, 0.f, 0.f);
        int i = s;
        for (; i + 2 <= e; i += 2) {
            int s0 = g_csr[i], s1 = g_csr[i + 1];
            f4add(a, T[s0 * 32 + lane]);
            f4add(a, T[s1 * 32 + lane]);
        }
        if (i < e) f4add(a, T[g_csr[i] * 32 + lane]);
        tot.x += fmaxf(a.x + bb.x, 0.f);
        tot.y += fmaxf(a.y + bb.y, 0.f);
        tot.z += fmaxf(a.z + bb.z, 0.f);
        tot.w += fmaxf(a.w + bb.w, 0.f);
    }
    atomicAdd(&s_acc[lane * 4 + 0], tot.x);
    atomicAdd(&s_acc[lane * 4 + 1], tot.y);
    atomicAdd(&s_acc[lane * 4 + 2], tot.z);
    atomicAdd(&s_acc[lane * 4 + 3], tot.w);
    __syncthreads();
    if (threadIdx.x < 128) atomicAdd(&g_acc[threadIdx.x], s_acc[threadIdx.x]);
}

__global__ void finalize_kernel(float* __restrict__ out) {
    int i = threadIdx.x;
    if (i < 128) out[i] = g_acc[i] * (1.0f / (float)N_NODES);
}

// ---------------------------------------------------------------------------
// fp32 SGEMM: C[M,N] = op(A[M,K] @ B[K,N] + bias), op = relu if do_relu
// A/C are internal ping-pong buffers selected by `ab`:
//   ab==0: A=g_bufA, C=g_bufB      ab==1: A=g_bufB, C=g_bufA
// BM=128, BN=128, BK=16, TM=TN=8, 256 threads
// ---------------------------------------------------------------------------
__global__ __launch_bounds__(256) void sgemm_kernel(
    const float* __restrict__ B, const float* __restrict__ bias,
    int M, int N, int K, int do_relu, int ab)
{
    constexpr int BM = 128, BN = 128, BK = 16, TM = 8, TN = 8;
    __shared__ float As[BK][BM];
    __shared__ float Bs[BK][BN];

    const float* __restrict__ A = ab ? g_bufB : g_bufA;
    float* __restrict__       C = ab ? g_bufA : g_bufB;

    const int tid   = threadIdx.x;
    const int brow0 = blockIdx.x * BM;
    const int bcol0 = blockIdx.y * BN;
    const int tr = (tid / (BN / TN)) * TM;   // 0..120
    const int tc = (tid % (BN / TN)) * TN;   // 0..120

    float acc[TM][TN];
#pragma unroll
    for (int i = 0; i < TM; i++)
#pragma unroll
        for (int j = 0; j < TN; j++) acc[i][j] = 0.f;

    for (int k0 = 0; k0 < K; k0 += BK) {
        // load A tile (BM x BK), stored transposed As[k][m]
#pragma unroll
        for (int l = 0; l < 2; l++) {
            int idx = tid + 256 * l;         // 0..511
            int row = idx >> 2;              // 0..127
            int kq  = (idx & 3) << 2;        // 0,4,8,12
            float4 v = make_float4(0.f, 0.f, 0.f, 0.f);
            int gr = brow0 + row;
            if (gr < M) v = *reinterpret_cast<const float4*>(&A[(size_t)gr * K + k0 + kq]);
            As[kq + 0][row] = v.x;
            As[kq + 1][row] = v.y;
            As[kq + 2][row] = v.z;
            As[kq + 3][row] = v.w;
        }
        // load B tile (BK x BN)
#pragma unroll
        for (int l = 0; l < 2; l++) {
            int idx = tid + 256 * l;
            int r   = idx >> 5;              // 0..15
            int c4  = (idx & 31) << 2;       // 0..124
            float4 v = *reinterpret_cast<const float4*>(&B[(size_t)(k0 + r) * N + bcol0 + c4]);
            *reinterpret_cast<float4*>(&Bs[r][c4]) = v;
        }
        __syncthreads();

#pragma unroll
        for (int kk = 0; kk < BK; kk++) {
            float a[TM], b[TN];
#pragma unroll
            for (int i = 0; i < TM; i += 4)
                *reinterpret_cast<float4*>(&a[i]) =
                    *reinterpret_cast<const float4*>(&As[kk][tr + i]);
#pragma unroll
            for (int j = 0; j < TN; j += 4)
                *reinterpret_cast<float4*>(&b[j]) =
                    *reinterpret_cast<const float4*>(&Bs[kk][tc + j]);
#pragma unroll
            for (int i = 0; i < TM; i++)
#pragma unroll
                for (int j = 0; j < TN; j++)
                    acc[i][j] = fmaf(a[i], b[j], acc[i][j]);
        }
        __syncthreads();
    }

    // epilogue: bias + relu + store
#pragma unroll
    for (int i = 0; i < TM; i++) {
        int gr = brow0 + tr + i;
        if (gr >= M) continue;
#pragma unroll
        for (int j = 0; j < TN; j += 4) {
            float4 v = make_float4(acc[i][j], acc[i][j + 1], acc[i][j + 2], acc[i][j + 3]);
            if (bias) {
                float4 bb = *reinterpret_cast<const float4*>(&bias[bcol0 + tc + j]);
                v.x += bb.x; v.y += bb.y; v.z += bb.z; v.w += bb.w;
            }
            if (do_relu) {
                v.x = fmaxf(v.x, 0.f); v.y = fmaxf(v.y, 0.f);
                v.z = fmaxf(v.z, 0.f); v.w = fmaxf(v.w, 0.f);
            }
            *reinterpret_cast<float4*>(&C[(size_t)gr * N + bcol0 + tc + j]) = v;
        }
    }
}

// ---------------------------------------------------------------------------
// launch
// ---------------------------------------------------------------------------
extern "C" void kernel_launch(void* const* d_in, const int* in_sizes, int n_in,
                              void* d_out, int out_size)
{
    const float* x   = (const float*)d_in[0];
    const int*   src = (const int*)  d_in[1];
    const int*   dst = (const int*)  d_in[2];
    const float* W1  = (const float*)d_in[3];
    const float* b1  = (const float*)d_in[4];
    const float* W2  = (const float*)d_in[5];
    const float* b2  = (const float*)d_in[6];
    const float* W3  = (const float*)d_in[7];
    const float* b3  = (const float*)d_in[8];
    float* out = (float*)d_out;
    (void)in_sizes; (void)n_in; (void)out_size;

    // CSR build
    zero_kernel   <<<(N_NODES + 255) / 256, 256>>>();
    hist_kernel   <<<(N_EDGES + 255) / 256, 256>>>(dst);
    scan_kernel   <<<1, 1024>>>();
    scatter_kernel<<<(N_EDGES + 255) / 256, 256>>>(src, dst);

    const int aggBlocks = (N_NODES + 7) / 8;   // 8 warps/block, 1 warp/node
    dim3 gemm2col((N_NODES + 127) / 128, 2);
    dim3 gemm1col((N_NODES + 127) / 128, 1);

    // layer 1: agg(x) -> bufA ; relu(bufA@W1+b1) -> bufB
    agg128_kernel<<<aggBlocks, 256>>>(x);
    sgemm_kernel<<<gemm2col, 256>>>(W1, b1, N_NODES, 256, 128, 1, 0);

    // layer 2: agg(bufB) -> bufA ; relu(bufA@W2+b2) -> bufB
    agg256_kernel<<<aggBlocks, 256>>>();
    sgemm_kernel<<<gemm2col, 256>>>(W2, b2, N_NODES, 256, 256, 1, 0);

    // layer 3 (reordered): bufB@W3 -> bufA ; mean_n relu(segsum(bufA) + b3)
    sgemm_kernel<<<gemm1col, 256>>>(W3, nullptr, N_NODES, 128, 256, 0, 1);
    agg_final_kernel<<<592, 256>>>(b3);
    finalize_kernel<<<1, 128>>>(out);
}